// round 3
// baseline (speedup 1.0000x reference)
#include <cuda_runtime.h>

typedef unsigned long long ull;

#define N_NODES 50000
#define IN_FEAT 64
#define HID 32
#define GRIDP 4
#define NG 128

// ---------------- scratch (static device globals; no allocs allowed) --------
__device__ float g_h[N_NODES * HID];
__device__ float g_T[N_NODES * HID];
__device__ float g_acc[N_NODES * HID];
__device__ float g_sums[NG * HID];
__device__ float g_cnt[NG];
__device__ int   g_is64;

// ---------------- helpers ---------------------------------------------------
__device__ __forceinline__ int ldidx(const void* p, long long i, int is64) {
    if (is64) return (int)__ldg((const long long*)p + i);
    return __ldg((const int*)p + i);
}

__device__ __forceinline__ ull pk2(float a, float b) {
    ull r; asm("mov.b64 %0, {%1,%2};" : "=l"(r) : "f"(a), "f"(b)); return r;
}
// Packed dual-fp32 FMA (2 full-precision fp32 FMAs per issue slot)
__device__ __forceinline__ ull ffma2(ull a, ull b, ull c) {
    ull d; asm("fma.rn.f32x2 %0, %1, %2, %3;" : "=l"(d) : "l"(a), "l"(b), "l"(c));
    return d;
}

__device__ __forceinline__ float lrelu(float v) { return v > 0.f ? v : 0.01f * v; }

// ---------------- init: zero pool buffers + detect index dtype --------------
__global__ void k_init(const void* ei) {
    int j = blockIdx.x * blockDim.x + threadIdx.x;
    if (j < NG * HID) g_sums[j] = 0.f;
    if (j < NG) g_cnt[j] = 0.f;
    if (j == 0) {
        const unsigned* a = (const unsigned*)ei;
        int is64 = 1;
        for (int i = 0; i < 32; i++)
            if (a[2 * i + 1] != 0u) is64 = 0;
        g_is64 = is64;
    }
}

// ---------------- Fourier-KAN projection -------------------------------------
// y[n,o] = sum_{i,g} cos((g+1)x[n,i])*W0[o,i,g] + sin((g+1)x[n,i])*W1[o,i,g]
// Each thread: 2 nodes x 8 output-pairs (one weight LDS feeds 2 nodes -> 1:4
// LDS:FFMA2, 16 independent accumulator chains).
// Weights repacked in shared: ull index ((s*IN+i)*16 + op)*4 + g, each ull =
// (w[2*op], w[2*op+1]) for that harmonic g.
// MODE 0: in = x,             out = g_h
// MODE 1: in = g_h,           out = g_T, zero g_acc
// MODE 2: in = lrelu(acc+h)   (writes h back), out = g_T, zero g_acc
template <int IN, int MODE>
__global__ __launch_bounds__(256) void k_kan(const float* __restrict__ xin,
                                             const float* __restrict__ W) {
    extern __shared__ float sw[];
    const int nW = 2 * HID * IN * GRIDP;
    for (int j = threadIdx.x; j < nW; j += blockDim.x) {
        int g = j & 3;
        int rem = j >> 2;
        int i = rem % IN;
        int o = (rem / IN) & (HID - 1);
        int s = rem / (IN * HID);
        sw[(((s * IN + i) * 16 + (o >> 1)) * 4 + g) * 2 + (o & 1)] = W[j];
    }
    __syncthreads();

    int tid = blockIdx.x * blockDim.x + threadIdx.x;
    if (tid >= N_NODES) return;          // 25000 pairs x 2 o-halves
    int pair = tid >> 1;
    int oh = tid & 1;                    // which 8 o-pairs this thread owns
    int n0 = pair * 2, n1 = n0 + 1;

    const ull* swu = (const ull*)sw;
    const int sinoff = IN * 64;          // ull units per s-block

    ull acc0[8], acc1[8];
#pragma unroll
    for (int t = 0; t < 8; t++) { acc0[t] = 0ull; acc1[t] = 0ull; }

    const float4* xp0 = (MODE == 0) ? (const float4*)(xin + (size_t)n0 * IN)
                                    : (const float4*)(g_h + n0 * HID);
    const float4* xp1 = (MODE == 0) ? (const float4*)(xin + (size_t)n1 * IN)
                                    : (const float4*)(g_h + n1 * HID);
    const float4* ap0 = (const float4*)(g_acc + n0 * HID);
    const float4* ap1 = (const float4*)(g_acc + n1 * HID);
    float4* hp0 = (float4*)(g_h + n0 * HID);
    float4* hp1 = (float4*)(g_h + n1 * HID);

#pragma unroll 1
    for (int ib = 0; ib < IN / 4; ib++) {
        float4 a4, b4;
        if (MODE == 2) {
            float4 m0 = ap0[ib], h0 = hp0[ib];
            a4.x = lrelu(m0.x + h0.x); a4.y = lrelu(m0.y + h0.y);
            a4.z = lrelu(m0.z + h0.z); a4.w = lrelu(m0.w + h0.w);
            hp0[ib] = a4;                // both o-half threads write same value
            float4 m1 = ap1[ib], h1 = hp1[ib];
            b4.x = lrelu(m1.x + h1.x); b4.y = lrelu(m1.y + h1.y);
            b4.z = lrelu(m1.z + h1.z); b4.w = lrelu(m1.w + h1.w);
            hp1[ib] = b4;
        } else {
            a4 = __ldg(xp0 + ib);
            b4 = __ldg(xp1 + ib);
        }
#pragma unroll
        for (int u = 0; u < 4; u++) {
            int i = ib * 4 + u;
            float xa = (&a4.x)[u], xb = (&b4.x)[u];
            float sa1, ca1, sb1, cb1;
            __sincosf(xa, &sa1, &ca1);
            __sincosf(xb, &sb1, &cb1);
            float ta = 2.f * ca1, tb = 2.f * cb1;
            float ca2 = fmaf(ta, ca1, -1.f), sa2 = ta * sa1;
            float ca3 = fmaf(ta, ca2, -ca1), sa3 = fmaf(ta, sa2, -sa1);
            float ca4 = fmaf(ta, ca3, -ca2), sa4 = fmaf(ta, sa3, -sa2);
            float cb2 = fmaf(tb, cb1, -1.f), sb2 = tb * sb1;
            float cb3 = fmaf(tb, cb2, -cb1), sb3 = fmaf(tb, sb2, -sb1);
            float cb4 = fmaf(tb, cb3, -cb2), sb4 = fmaf(tb, sb3, -sb2);
            ull Ca[4] = { pk2(ca1, ca1), pk2(ca2, ca2), pk2(ca3, ca3), pk2(ca4, ca4) };
            ull Sa[4] = { pk2(sa1, sa1), pk2(sa2, sa2), pk2(sa3, sa3), pk2(sa4, sa4) };
            ull Cb[4] = { pk2(cb1, cb1), pk2(cb2, cb2), pk2(cb3, cb3), pk2(cb4, cb4) };
            ull Sb[4] = { pk2(sb1, sb1), pk2(sb2, sb2), pk2(sb3, sb3), pk2(sb4, sb4) };
            const ulonglong2* pc = (const ulonglong2*)(swu + ((size_t)i * 16 + oh * 8) * 4);
            const ulonglong2* ps = (const ulonglong2*)(swu + sinoff + ((size_t)i * 16 + oh * 8) * 4);
#pragma unroll
            for (int op = 0; op < 8; op++) {
                ulonglong2 w01 = pc[op * 2], w23 = pc[op * 2 + 1];
                ull p0 = acc0[op], p1 = acc1[op];
                p0 = ffma2(Ca[0], w01.x, p0);  p1 = ffma2(Cb[0], w01.x, p1);
                p0 = ffma2(Ca[1], w01.y, p0);  p1 = ffma2(Cb[1], w01.y, p1);
                p0 = ffma2(Ca[2], w23.x, p0);  p1 = ffma2(Cb[2], w23.x, p1);
                p0 = ffma2(Ca[3], w23.y, p0);  p1 = ffma2(Cb[3], w23.y, p1);
                ulonglong2 v01 = ps[op * 2], v23 = ps[op * 2 + 1];
                p0 = ffma2(Sa[0], v01.x, p0);  p1 = ffma2(Sb[0], v01.x, p1);
                p0 = ffma2(Sa[1], v01.y, p0);  p1 = ffma2(Sb[1], v01.y, p1);
                p0 = ffma2(Sa[2], v23.x, p0);  p1 = ffma2(Sb[2], v23.x, p1);
                p0 = ffma2(Sa[3], v23.y, p0);  p1 = ffma2(Sb[3], v23.y, p1);
                acc0[op] = p0; acc1[op] = p1;
            }
        }
    }

    float* outbase = (MODE == 0) ? g_h : g_T;
    ulonglong2* po0 = (ulonglong2*)(outbase + n0 * HID) + oh * 4;
    ulonglong2* po1 = (ulonglong2*)(outbase + n1 * HID) + oh * 4;
#pragma unroll
    for (int j = 0; j < 4; j++) {
        po0[j] = make_ulonglong2(acc0[2 * j], acc0[2 * j + 1]);
        po1[j] = make_ulonglong2(acc1[2 * j], acc1[2 * j + 1]);
    }

    if (MODE != 0) {  // zero scatter buffer rows (each o-half zeroes its half)
        float4 z = make_float4(0.f, 0.f, 0.f, 0.f);
        float4* az0 = (float4*)(g_acc + n0 * HID) + oh * 4;
        float4* az1 = (float4*)(g_acc + n1 * HID) + oh * 4;
#pragma unroll
        for (int j = 0; j < 4; j++) { az0[j] = z; az1[j] = z; }
    }
}

// ---------------- edge scatter: acc[dst] += T[src] --------------------------
// 8 lanes per edge, one float4 each (simple per-lane index loads: R1-measured
// faster than shuffle dedup).
__global__ void k_scatter(const void* __restrict__ ei, int E) {
    long long gid = (long long)blockIdx.x * blockDim.x + threadIdx.x;
    int e = (int)(gid >> 3);
    int q = (int)(gid & 7);
    if (e >= E) return;
    int is64 = g_is64;
    int src = ldidx(ei, e, is64);
    int dst = ldidx(ei, (long long)E + e, is64);
    float4 v = __ldg((const float4*)g_T + src * (HID / 4) + q);
    float* p = g_acc + dst * HID + q * 4;
    asm volatile("red.global.add.v4.f32 [%0], {%1, %2, %3, %4};"
                 :: "l"(p), "f"(v.x), "f"(v.y), "f"(v.z), "f"(v.w)
                 : "memory");
}

// ---------------- pooling (fused final leaky-relu + residual) ---------------
__global__ void k_pool(const void* __restrict__ batch) {
    int warp = (blockIdx.x * blockDim.x + threadIdx.x) >> 5;
    int lane = threadIdx.x & 31;
    if (warp >= N_NODES) return;
    int b = ldidx(batch, warp, g_is64);
    float m = g_acc[warp * HID + lane];
    float h = g_h[warp * HID + lane];
    float v = lrelu(m + h);
    atomicAdd(&g_sums[b * HID + lane], v);
    if (lane == 0) atomicAdd(&g_cnt[b], 1.f);
}

// ---------------- readout: sigmoid(KAN_linear(mean_pool)) -------------------
__global__ void k_readout(const float* __restrict__ Wout,
                          const float* __restrict__ bout,
                          float* __restrict__ out) {
    int g = threadIdx.x;
    if (g >= NG) return;
    float cnt = fmaxf(g_cnt[g], 1.f);
    float inv = 1.f / cnt;
    float acc = 0.f;
#pragma unroll
    for (int c = 0; c < HID; c++) {
        float y = g_sums[g * HID + c] * inv;
        float s, co;
        __sincosf(y, &s, &co);
        acc = fmaf(co, Wout[c], acc);
        acc = fmaf(s, Wout[HID + c], acc);
    }
    acc += bout[0];
    out[g] = 1.f / (1.f + __expf(-acc));
}

// ---------------- launch ----------------------------------------------------
extern "C" void kernel_launch(void* const* d_in, const int* in_sizes, int n_in,
                              void* d_out, int out_size) {
    const float* x      = (const float*)d_in[0];
    const void*  ei     = d_in[1];
    const void*  batch  = d_in[2];
    const float* W_in   = (const float*)d_in[3];
    const float* W_conv = (const float*)d_in[4];
    const float* W_out  = (const float*)d_in[5];
    const float* b_out  = (const float*)d_in[6];
    float* out = (float*)d_out;

    int E = in_sizes[1] / 2;

    cudaFuncSetAttribute(k_kan<IN_FEAT, 0>,
                         cudaFuncAttributeMaxDynamicSharedMemorySize, 65536);

    k_init<<<16, 256>>>(ei);

    int nb = (N_NODES + 255) / 256;
    k_kan<IN_FEAT, 0><<<nb, 256, 2 * HID * IN_FEAT * GRIDP * sizeof(float)>>>(x, W_in);

    const int convW = 2 * HID * HID * GRIDP;
    long long tthreads = (long long)E * 8;
    int sb = (int)((tthreads + 255) / 256);

    // layer 0: transform h -> T, scatter
    k_kan<HID, 1><<<nb, 256, convW * sizeof(float)>>>(nullptr, W_conv);
    k_scatter<<<sb, 256>>>(ei, E);

    // layer 1: fused lrelu(acc+h) -> transform -> T, scatter
    k_kan<HID, 2><<<nb, 256, convW * sizeof(float)>>>(nullptr, W_conv + convW);
    k_scatter<<<sb, 256>>>(ei, E);

    k_pool<<<(N_NODES + 7) / 8, 256>>>(batch);
    k_readout<<<1, 128>>>(W_out, b_out, out);
}